// round 16
// baseline (speedup 1.0000x reference)
#include <cuda_runtime.h>
#include <cuda_bf16.h>
#include <stdint.h>
#include <math.h>

#define B_ 8
#define N_ 2048
#define M_ 256
#define Q_ 16384
#define D_ 32
#define K_ 16
#define H_ 64
#define LAM_ 5.0f
#define CG_ITERS_ 20
#define RADIUS_ 0.005859375f   // 1.5/256

#define C0_OFF 131072
#define C_OFF  196608

__device__ float g_gw[B_][D_];

// ---------------- helpers ----------------
__device__ __forceinline__ uint32_t smem_u32(const void* p) {
    return (uint32_t)__cvta_generic_to_shared(p);
}
__device__ __forceinline__ uint32_t mapa_rank(uint32_t addr, uint32_t rank) {
    uint32_t r;
    asm("mapa.shared::cluster.u32 %0, %1, %2;" : "=r"(r) : "r"(addr), "r"(rank));
    return r;
}
__device__ __forceinline__ void st_cluster(uint32_t addr, float v) {
    asm volatile("st.shared::cluster.f32 [%0], %1;" :: "r"(addr), "f"(v));
}
__device__ __forceinline__ void cluster_arrive_() {
    asm volatile("barrier.cluster.arrive.aligned;" ::: "memory");
}
__device__ __forceinline__ void cluster_wait_() {
    asm volatile("barrier.cluster.wait.aligned;" ::: "memory");
}

__global__ void nop_kernel() {}   // keeps ncu capture slot (index 6) on cg kernel

// ---------------- kernel 1: global gate ----------------
__global__ void __launch_bounds__(1024) g_kernel(
    const float* __restrict__ xs, const float* __restrict__ us,
    const float* __restrict__ Wg1, const float* __restrict__ bg1,
    const float* __restrict__ Wg2, const float* __restrict__ bg2)
{
    int b = blockIdx.x, t = threadIdx.x;
    int h = t & 63, grp = t >> 6;
    float w0 = Wg1[h], w1 = Wg1[H_ + h], bb = bg1[h];
    float acc = 0.f;
    const float* xb = xs + b * N_;
    const float* ub = us + b * N_;
    int nbeg = grp * 128, nend = nbeg + 128;
#pragma unroll 4
    for (int n = nbeg; n < nend; n++)
        acc += fmaxf(fmaf(xb[n], w0, fmaf(ub[n], w1, bb)), 0.f);
    __shared__ float red[16][H_];
    __shared__ float gh[H_];
    red[grp][h] = acc;
    __syncthreads();
    if (t < H_) {
        float s = 0.f;
#pragma unroll
        for (int g = 0; g < 16; g++) s += red[g][t];
        gh[t] = s * (1.0f / (float)N_);
    }
    __syncthreads();
    if (t < D_) {
        float v = bg2[t];
#pragma unroll 8
        for (int hh = 0; hh < H_; hh++) v = fmaf(gh[hh], Wg2[hh * D_ + t], v);
        g_gw[b][t] = v;
    }
}

// ---------------- kernel 2: encode ----------------
__global__ void __launch_bounds__(256) encode_kernel(
    const float* __restrict__ xs, const float* __restrict__ us,
    const float* __restrict__ centers,
    const float* __restrict__ W1, const float* __restrict__ b1,
    const float* __restrict__ W2, const float* __restrict__ b2,
    const float* __restrict__ W3, const float* __restrict__ b3,
    const int* __restrict__ idx, float* __restrict__ out)
{
    __shared__ float W2s[H_ * H_];
    __shared__ __align__(16) float h1T[4][H_ * K_];
    __shared__ float rel_s[4][K_], u_s[4][K_];
    __shared__ float hb[4][H_];

    int u = threadIdx.x >> 6;
    int lt = threadIdx.x & 63;
    int bm = blockIdx.x * 4 + u;
    int b = bm >> 8, m = bm & 255;

    {
        const float4* src = (const float4*)W2;
        float4* dst = (float4*)W2s;
#pragma unroll
        for (int i = 0; i < 4; i++) dst[threadIdx.x + i * 256] = src[threadIdx.x + i * 256];
    }
    if (lt < K_) {
        int sj = idx[m * K_ + lt];
        rel_s[u][lt] = (xs[b * N_ + sj] - centers[m]) / RADIUS_;
        u_s[u][lt] = us[b * N_ + sj];
    }
    __syncthreads();

    {
        float w10 = W1[lt], w11 = W1[H_ + lt], bb1 = b1[lt];
#pragma unroll
        for (int k = 0; k < K_; k++)
            h1T[u][lt * K_ + k] = fmaxf(fmaf(rel_s[u][k], w10, fmaf(u_s[u][k], w11, bb1)), 0.f);
    }
    __syncthreads();

    {
        float acc[K_];
        float bb2 = b2[lt];
#pragma unroll
        for (int k = 0; k < K_; k++) acc[k] = bb2;
        for (int jj = 0; jj < H_; jj++) {
            float wv = W2s[jj * H_ + lt];
            const float4* hp = (const float4*)(h1T[u] + jj * K_);
#pragma unroll
            for (int kk = 0; kk < 4; kk++) {
                float4 h4 = hp[kk];
                acc[kk * 4 + 0] = fmaf(h4.x, wv, acc[kk * 4 + 0]);
                acc[kk * 4 + 1] = fmaf(h4.y, wv, acc[kk * 4 + 1]);
                acc[kk * 4 + 2] = fmaf(h4.z, wv, acc[kk * 4 + 2]);
                acc[kk * 4 + 3] = fmaf(h4.w, wv, acc[kk * 4 + 3]);
            }
        }
        float accm = 0.f;
#pragma unroll
        for (int k = 0; k < K_; k++) accm += fmaxf(acc[k], 0.f);
        hb[u][lt] = accm * (1.0f / (float)K_);
    }
    __syncthreads();

    if (lt < D_) {
        float v = b3[lt];
#pragma unroll 8
        for (int h = 0; h < H_; h++) v = fmaf(hb[u][h], W3[h * D_ + lt], v);
        out[C0_OFF + bm * D_ + lt] = v + g_gw[b][lt];
    }
}

// ---------------- kernel 3: sheaf CG (register-R fold; NODES per CTA templated) ----------------
#define NT_CG 544   // 17 warps

__device__ __forceinline__ void edge_r_fn(const float (&Rs)[16], const float (&Rd)[16],
    const float* __restrict__ r_s, int rowA, float* __restrict__ re, int lane, int riMap)
{
    float a = r_s[rowA * 32 + lane];
    float c = r_s[rowA * 32 + 32 + lane];
    float v[16];
#pragma unroll
    for (int ri = 0; ri < 16; ri++) { v[ri] = Rs[ri] * a; v[ri] = fmaf(-Rd[ri], c, v[ri]); }
    {
        const bool bb = (lane & 16) != 0;
#pragma unroll
        for (int t = 0; t < 8; t++) {
            float snd = bb ? v[t] : v[t + 8];
            float kp  = bb ? v[t + 8] : v[t];
            v[t] = kp + __shfl_xor_sync(0xffffffffu, snd, 16);
        }
    }
    {
        const bool bb = (lane & 8) != 0;
#pragma unroll
        for (int t = 0; t < 4; t++) {
            float snd = bb ? v[t] : v[t + 4];
            float kp  = bb ? v[t + 4] : v[t];
            v[t] = kp + __shfl_xor_sync(0xffffffffu, snd, 8);
        }
    }
    {
        const bool bb = (lane & 4) != 0;
#pragma unroll
        for (int t = 0; t < 2; t++) {
            float snd = bb ? v[t] : v[t + 2];
            float kp  = bb ? v[t + 2] : v[t];
            v[t] = kp + __shfl_xor_sync(0xffffffffu, snd, 4);
        }
    }
    {
        const bool bb = (lane & 2) != 0;
        float snd = bb ? v[0] : v[1];
        float kp  = bb ? v[1] : v[0];
        v[0] = kp + __shfl_xor_sync(0xffffffffu, snd, 2);
    }
    v[0] += __shfl_xor_sync(0xffffffffu, v[0], 1);
    if ((lane & 1) == 0) re[riMap] = v[0];
}

__device__ __forceinline__ void edge_g_fn(const float (&Rs)[16], const float (&Rd)[16],
    const float* __restrict__ re, float* __restrict__ gs_o, float* __restrict__ gd_o, int lane)
{
    float gs = 0.f, gd = 0.f;
#pragma unroll
    for (int ri = 0; ri < 16; ri++) {
        float rv = re[ri];
        gs = fmaf(Rs[ri], rv, gs);
        gd = fmaf(Rd[ri], rv, gd);
    }
    gs_o[lane] = gs;
    gd_o[lane] = gd;
}

template<int NODES>
__global__ void __launch_bounds__(NT_CG, 1) cg_kernel_t(
    const float* __restrict__ Rsrc, const float* __restrict__ Rdst,
    float* __restrict__ out)
{
    constexpr int CPB  = M_ / NODES;      // CTAs per batch (cluster size)
    constexpr int EPW  = NODES / 16;      // edges per warp (1 or 2)
    constexpr int MAXE = NODES + 1;
    constexpr int NEL  = NODES * 32;

    __shared__ float r_s[(NODES + 2) * 32];   // rows 0 / NODES+1 = halos
    __shared__ float w_s[NEL];
    __shared__ float p_s[NEL];
    __shared__ float s_s[NEL];
    __shared__ float x_s[NEL];
    __shared__ float sh_[2][32];
    __shared__ float redge[MAXE * 16];
    __shared__ float gse[MAXE * 32], gde[MAXE * 32];
    __shared__ float part_in[2][CPB][2];
    __shared__ float rin[2][32];
    __shared__ float wb[2][2][32];
    __shared__ float wred[17][2];

    const int b = blockIdx.x / CPB, j = blockIdx.x % CPB;
    const int tid = threadIdx.x, w = tid >> 5, lane = tid & 31;
    const int n0 = j * NODES;
    const int eA = j ? (n0 - 1) : 0;
    const int eB = (n0 + NODES - 1) < 254 ? (n0 + NODES - 1) : 254;
    const int nE = eB - eA + 1;
    const int riMap = ((lane >> 4) & 1) * 8 + ((lane >> 3) & 1) * 4 +
                      ((lane >> 2) & 1) * 2 + ((lane >> 1) & 1);

    const int el0 = EPW * w, el1 = el0 + 1;
    const bool h0 = el0 < nE;
    const bool h1 = (EPW == 2) && (el1 < nE);
    const int row0 = eA + el0 - n0 + 1;
    const int row1 = row0 + 1;

    float Rs0[16], Rd0[16], Rs1[16], Rd1[16];
    if (h0) {
        const float* a = Rsrc + (size_t)(eA + el0) * 512 + lane;
        const float* d = Rdst + (size_t)(eA + el0) * 512 + lane;
#pragma unroll
        for (int ri = 0; ri < 16; ri++) { Rs0[ri] = a[ri * 32]; Rd0[ri] = d[ri * 32]; }
    }
    if constexpr (EPW == 2) {
        if (h1) {
            const float* a = Rsrc + (size_t)(eA + el1) * 512 + lane;
            const float* d = Rdst + (size_t)(eA + el1) * 512 + lane;
#pragma unroll
            for (int ri = 0; ri < 16; ri++) { Rs1[ri] = a[ri * 32]; Rd1[ri] = d[ri * 32]; }
        }
    }

    auto apply_fused = [&](float& lg, float& ld) {
        if (h0) edge_r_fn(Rs0, Rd0, r_s, row0, &redge[el0 * 16], lane, riMap);
        if constexpr (EPW == 2) { if (h1) edge_r_fn(Rs1, Rd1, r_s, row1, &redge[el1 * 16], lane, riMap); }
        __syncwarp();
        if (h0) edge_g_fn(Rs0, Rd0, &redge[el0 * 16], &gse[el0 * 32], &gde[el0 * 32], lane);
        if constexpr (EPW == 2) { if (h1) edge_g_fn(Rs1, Rd1, &redge[el1 * 16], &gse[el1 * 32], &gde[el1 * 32], lane); }
        __syncthreads();
        for (int i = tid; i < NEL; i += NT_CG) {
            int n = n0 + (i >> 5), d = i & 31;
            float acc = 0.f;
            if (n <= 254) acc = gse[(n - eA) * 32 + d];
            if (n >= 1)  acc -= gde[(n - 1 - eA) * 32 + d];
            float rr = r_s[i + 32];
            float ww = fmaf(LAM_, acc, rr);
            w_s[i] = ww;
            lg = fmaf(rr, rr, lg);
            ld = fmaf(rr, ww, ld);
        }
    };
    auto reduce_export = [&](float lg, float ld, int buf) {
#pragma unroll
        for (int o = 16; o; o >>= 1) {
            lg += __shfl_xor_sync(0xffffffffu, lg, o);
            ld += __shfl_xor_sync(0xffffffffu, ld, o);
        }
        if (lane == 0) { wred[w][0] = lg; wred[w][1] = ld; }
        __syncthreads();
        if (tid < CPB) {
            float sg = 0.f, sd = 0.f;
#pragma unroll
            for (int k2 = 0; k2 < 17; k2++) { sg += wred[k2][0]; sd += wred[k2][1]; }
            st_cluster(mapa_rank(smem_u32(&part_in[buf][j][0]), (uint32_t)tid), sg);
            st_cluster(mapa_rank(smem_u32(&part_in[buf][j][1]), (uint32_t)tid), sd);
        }
    };
    auto whalo_send = [&](int buf) {
        if (tid >= 64 && tid < 96) {
            if (j > 0) st_cluster(mapa_rank(smem_u32(&wb[buf][1][tid - 64]), j - 1), w_s[tid - 64]);
        } else if (tid >= 96 && tid < 128) {
            if (j < CPB - 1) st_cluster(mapa_rank(smem_u32(&wb[buf][0][tid - 96]), j + 1),
                                        w_s[(NODES - 1) * 32 + tid - 96]);
        }
    };

    // ---- prolog ----
    const float* c0g = out + C0_OFF + b * (M_ * D_);
    for (int i = tid; i < (NODES + 2) * 32; i += NT_CG) {
        int node = n0 - 1 + (i >> 5);
        r_s[i] = (node >= 0 && node < M_) ? c0g[node * 32 + (i & 31)] : 0.f;
    }
    __syncthreads();
    for (int i = tid; i < NEL; i += NT_CG) x_s[i] = r_s[i + 32];
    __syncthreads();

    { float z0 = 0, z1 = 0; apply_fused(z0, z1); }   // w = A c0
    __syncthreads();
    for (int i = tid; i < NEL; i += NT_CG) r_s[i + 32] = x_s[i] - w_s[i];
    __syncthreads();

    // r0 halo exchange
    if (tid < 32) {
        if (j > 0) st_cluster(mapa_rank(smem_u32(&rin[1][tid]), j - 1), r_s[32 + tid]);
    } else if (tid < 64) {
        if (j < CPB - 1) st_cluster(mapa_rank(smem_u32(&rin[0][tid - 32]), j + 1), r_s[NODES * 32 + tid - 32]);
    }
    cluster_arrive_(); cluster_wait_();
    if (tid < 32) {
        if (j > 0) r_s[tid] = rin[0][tid];
    } else if (tid < 64) {
        if (j < CPB - 1) r_s[(NODES + 1) * 32 + (tid - 32)] = rin[1][tid - 32];
    }
    __syncthreads();

    float lg = 0.f, ld = 0.f;
    apply_fused(lg, ld);
    reduce_export(lg, ld, 0);
    whalo_send(0);
    cluster_arrive_(); cluster_wait_();

    float gam = 0.f, del = 0.f;
#pragma unroll
    for (int k2 = 0; k2 < CPB; k2++) { gam += part_in[0][k2][0]; del += part_in[0][k2][1]; }
    float alpha = gam / (del + 1e-12f);
    float gam_prev = gam, alpha_prev = alpha;
    float alphap = alpha;

    if (tid < 32) {
        if (j > 0) {
            float sv = wb[0][0][tid];
            sh_[0][tid] = sv;
            r_s[tid] = fmaf(-alpha, sv, r_s[tid]);
        }
    } else if (tid < 64) {
        if (j < CPB - 1) {
            int d2 = tid - 32;
            float sv = wb[0][1][d2];
            sh_[1][d2] = sv;
            r_s[(NODES + 1) * 32 + d2] = fmaf(-alpha, sv, r_s[(NODES + 1) * 32 + d2]);
        }
    }
    for (int i = tid; i < NEL; i += NT_CG) {
        float rr = r_s[i + 32], ww = w_s[i];
        p_s[i] = rr; s_s[i] = ww;
        r_s[i + 32] = fmaf(-alpha, ww, rr);
    }
    __syncthreads();

    // ---- main loop: ONE cluster sync per iteration ----
    for (int it = 1; it < CG_ITERS_; it++) {
        float g0 = 0.f, d0 = 0.f;
        apply_fused(g0, d0);
        const int buf = it & 1;
        reduce_export(g0, d0, buf);
        if (it < CG_ITERS_ - 1) whalo_send(buf);
        cluster_arrive_();
        for (int i = tid; i < NEL; i += NT_CG)
            x_s[i] = fmaf(alphap, p_s[i], x_s[i]);
        cluster_wait_();

        gam = 0.f; del = 0.f;
#pragma unroll
        for (int k2 = 0; k2 < CPB; k2++) { gam += part_in[buf][k2][0]; del += part_in[buf][k2][1]; }
        float beta = gam / (gam_prev + 1e-12f);
        alpha = gam / (del - beta * gam / alpha_prev + 1e-12f);
        gam_prev = gam; alpha_prev = alpha;

        if (it == CG_ITERS_ - 1) {
            float* og = out + C_OFF + b * (M_ * D_) + n0 * 32;
            for (int i = tid; i < NEL; i += NT_CG)
                og[i] = fmaf(alpha, fmaf(beta, p_s[i], r_s[i + 32]), x_s[i]);
            return;
        }
        alphap = alpha;

        if (tid < 32) {
            if (j > 0) {
                float sv = fmaf(beta, sh_[0][tid], wb[buf][0][tid]);
                sh_[0][tid] = sv;
                r_s[tid] = fmaf(-alpha, sv, r_s[tid]);
            }
        } else if (tid < 64) {
            if (j < CPB - 1) {
                int d2 = tid - 32;
                float sv = fmaf(beta, sh_[1][d2], wb[buf][1][d2]);
                sh_[1][d2] = sv;
                r_s[(NODES + 1) * 32 + d2] = fmaf(-alpha, sv, r_s[(NODES + 1) * 32 + d2]);
            }
        }
        for (int i = tid; i < NEL; i += NT_CG) {
            float rr = r_s[i + 32], ww = w_s[i];
            float pp = fmaf(beta, p_s[i], rr);
            float ss = fmaf(beta, s_s[i], ww);
            r_s[i + 32] = fmaf(-alpha, ss, rr);
            p_s[i] = pp; s_s[i] = ss;
        }
        __syncthreads();
    }
}

// ---------------- kernel 4: query eval ----------------
__global__ void __launch_bounds__(256) query_kernel(
    const float* __restrict__ phi_q, const float* __restrict__ out_c,
    float* __restrict__ out)
{
    __shared__ float4 c_s[512];
    int q0 = blockIdx.x * 64;
    int mbase = (int)floorf((q0 + 0.5f) * 0.015625f) - 2;
    if (mbase < 0) mbase = 0;
    if (mbase > M_ - 8) mbase = M_ - 8;

    const float4* cg4 = (const float4*)out_c;
    for (int i = threadIdx.x; i < 512; i += 256) {
        int mm = i >> 6, rem = i & 63;
        int bb2 = rem >> 3, d4 = rem & 7;
        c_s[i] = cg4[((size_t)bb2 * M_ + (mbase + mm)) * 8 + d4];
    }
    __syncthreads();

    int ql = threadIdx.x >> 2;
    int dh = (threadIdx.x >> 1) & 1;
    int bh = threadIdx.x & 1;
    int q = q0 + ql;
    float v = (q + 0.5f) * 0.015625f;
    int mlo = (int)floorf(v) - 1;

    float wr[3];
    float4 p4[3][4];
    int mc[3];
#pragma unroll
    for (int c = 0; c < 3; c++) {
        int m = mlo + c;
        int mcl = m < 0 ? 0 : (m > M_ - 1 ? M_ - 1 : m);
        mc[c] = mcl;
        const float4* ph = (const float4*)(phi_q + ((size_t)mcl * Q_ + q) * 32) + dh * 4;
        p4[c][0] = __ldg(ph + 0);
        p4[c][1] = __ldg(ph + 1);
        p4[c][2] = __ldg(ph + 2);
        p4[c][3] = __ldg(ph + 3);
        float t = (v - (m + 0.5f)) * (1.0f / 1.5f);
        float w_ = 1.0f - fabsf(t);
        wr[c] = (m >= 0 && m <= M_ - 1) ? fmaxf(w_, 0.f) : 0.f;
    }
    float wsum = wr[0] + wr[1] + wr[2];

    float sacc[4] = {0.f, 0.f, 0.f, 0.f};
#pragma unroll
    for (int c = 0; c < 3; c++) {
        int ms = mc[c] - mbase;
#pragma unroll
        for (int bb2 = 0; bb2 < 4; bb2++) {
            const float4* cc = &c_s[(ms << 6) + ((bh * 4 + bb2) << 3) + dh * 4];
            float dot = 0.f;
#pragma unroll
            for (int i = 0; i < 4; i++) {
                float4 c4 = cc[i];
                float4 pp = p4[c][i];
                dot = fmaf(pp.x, c4.x, dot);
                dot = fmaf(pp.y, c4.y, dot);
                dot = fmaf(pp.z, c4.z, dot);
                dot = fmaf(pp.w, c4.w, dot);
            }
            sacc[bb2] = fmaf(wr[c], dot, sacc[bb2]);
        }
    }
#pragma unroll
    for (int bb2 = 0; bb2 < 4; bb2++)
        sacc[bb2] += __shfl_xor_sync(0xffffffffu, sacc[bb2], 2);
    if (dh == 0) {
        float inv = 1.0f / fmaxf(wsum, 1e-8f);
#pragma unroll
        for (int bb2 = 0; bb2 < 4; bb2++)
            out[(size_t)(bh * 4 + bb2) * Q_ + q] = sacc[bb2] * inv;
    }
}

// ---------------- launch ----------------
extern "C" void kernel_launch(void* const* d_in, const int* in_sizes, int n_in,
                              void* d_out, int out_size) {
    const float* xs      = (const float*)d_in[0];
    const float* us      = (const float*)d_in[1];
    const float* phi_q   = (const float*)d_in[2];
    const float* centers = (const float*)d_in[4];
    const float* R_src   = (const float*)d_in[5];
    const float* R_dst   = (const float*)d_in[6];
    const float* W1      = (const float*)d_in[7];
    const float* b1      = (const float*)d_in[8];
    const float* W2      = (const float*)d_in[9];
    const float* b2      = (const float*)d_in[10];
    const float* W3      = (const float*)d_in[11];
    const float* b3      = (const float*)d_in[12];
    const float* Wg1     = (const float*)d_in[13];
    const float* bg1     = (const float*)d_in[14];
    const float* Wg2     = (const float*)d_in[15];
    const float* bg2     = (const float*)d_in[16];
    const int*   idx     = (const int*)d_in[17];
    float* out = (float*)d_out;

    nop_kernel<<<1, 32>>>();
    g_kernel<<<B_, 1024>>>(xs, us, Wg1, bg1, Wg2, bg2);
    encode_kernel<<<B_ * M_ / 4, 256>>>(xs, us, centers, W1, b1, W2, b2, W3, b3, idx, out);

    // Prefer 16-CTA clusters (128 SMs); fall back to the proven 8-CTA layout.
    cudaFuncSetAttribute(cg_kernel_t<16>, cudaFuncAttributeNonPortableClusterSizeAllowed, 1);
    cudaLaunchConfig_t cfg = {};
    cfg.gridDim = dim3(B_ * 16, 1, 1);
    cfg.blockDim = dim3(NT_CG, 1, 1);
    cudaLaunchAttribute attrs[1];
    attrs[0].id = cudaLaunchAttributeClusterDimension;
    attrs[0].val.clusterDim = {16, 1, 1};
    cfg.attrs = attrs;
    cfg.numAttrs = 1;
    cfg.stream = 0;

    int maxC = 0;
    cudaOccupancyMaxPotentialClusterSize(&maxC, cg_kernel_t<16>, &cfg);
    if (maxC >= 16) {
        cudaLaunchKernelEx(&cfg, cg_kernel_t<16>, R_src, R_dst, out);
    } else {
        cudaLaunchConfig_t cfg8 = cfg;
        cfg8.gridDim = dim3(B_ * 8, 1, 1);
        attrs[0].val.clusterDim = {8, 1, 1};
        cudaLaunchKernelEx(&cfg8, cg_kernel_t<32>, R_src, R_dst, out);
    }

    query_kernel<<<Q_ / 64, 256>>>(phi_q, out + C_OFF, out);
}

// round 17
// speedup vs baseline: 1.3194x; 1.3194x over previous
#include <cuda_runtime.h>
#include <cuda_bf16.h>
#include <stdint.h>
#include <math.h>

#define B_ 8
#define N_ 2048
#define M_ 256
#define Q_ 16384
#define D_ 32
#define K_ 16
#define H_ 64
#define LAM_ 5.0f
#define CG_ITERS_ 20
#define RADIUS_ 0.005859375f   // 1.5/256

#define C0_OFF 131072
#define C_OFF  196608

__device__ float g_gw[B_][D_];

// ---------------- helpers ----------------
__device__ __forceinline__ uint32_t smem_u32(const void* p) {
    return (uint32_t)__cvta_generic_to_shared(p);
}
__device__ __forceinline__ uint32_t mapa_rank(uint32_t addr, uint32_t rank) {
    uint32_t r;
    asm("mapa.shared::cluster.u32 %0, %1, %2;" : "=r"(r) : "r"(addr), "r"(rank));
    return r;
}
__device__ __forceinline__ void st_cluster(uint32_t addr, float v) {
    asm volatile("st.shared::cluster.f32 [%0], %1;" :: "r"(addr), "f"(v));
}
__device__ __forceinline__ void cluster_arrive_() {
    asm volatile("barrier.cluster.arrive.aligned;" ::: "memory");
}
__device__ __forceinline__ void cluster_wait_() {
    asm volatile("barrier.cluster.wait.aligned;" ::: "memory");
}

// ---------------- kernel 1: global gate ----------------
__global__ void __launch_bounds__(1024) g_kernel(
    const float* __restrict__ xs, const float* __restrict__ us,
    const float* __restrict__ Wg1, const float* __restrict__ bg1,
    const float* __restrict__ Wg2, const float* __restrict__ bg2)
{
    int b = blockIdx.x, t = threadIdx.x;
    int h = t & 63, grp = t >> 6;
    float w0 = Wg1[h], w1 = Wg1[H_ + h], bb = bg1[h];
    float acc = 0.f;
    const float* xb = xs + b * N_;
    const float* ub = us + b * N_;
    int nbeg = grp * 128, nend = nbeg + 128;
#pragma unroll 4
    for (int n = nbeg; n < nend; n++)
        acc += fmaxf(fmaf(xb[n], w0, fmaf(ub[n], w1, bb)), 0.f);
    __shared__ float red[16][H_];
    __shared__ float gh[H_];
    red[grp][h] = acc;
    __syncthreads();
    if (t < H_) {
        float s = 0.f;
#pragma unroll
        for (int g = 0; g < 16; g++) s += red[g][t];
        gh[t] = s * (1.0f / (float)N_);
    }
    __syncthreads();
    if (t < D_) {
        float v = bg2[t];
#pragma unroll 8
        for (int hh = 0; hh < H_; hh++) v = fmaf(gh[hh], Wg2[hh * D_ + t], v);
        g_gw[b][t] = v;
    }
}

// ---------------- kernel 2: encode (PDL: g_gw read deferred past griddep sync) ----------------
__global__ void __launch_bounds__(256) encode_kernel(
    const float* __restrict__ xs, const float* __restrict__ us,
    const float* __restrict__ centers,
    const float* __restrict__ W1, const float* __restrict__ b1,
    const float* __restrict__ W2, const float* __restrict__ b2,
    const float* __restrict__ W3, const float* __restrict__ b3,
    const int* __restrict__ idx, float* __restrict__ out)
{
    __shared__ float W2s[H_ * H_];
    __shared__ __align__(16) float h1T[4][H_ * K_];
    __shared__ float rel_s[4][K_], u_s[4][K_];
    __shared__ float hb[4][H_];

    int u = threadIdx.x >> 6;
    int lt = threadIdx.x & 63;
    int bm = blockIdx.x * 4 + u;
    int b = bm >> 8, m = bm & 255;

    {
        const float4* src = (const float4*)W2;
        float4* dst = (float4*)W2s;
#pragma unroll
        for (int i = 0; i < 4; i++) dst[threadIdx.x + i * 256] = src[threadIdx.x + i * 256];
    }
    if (lt < K_) {
        int sj = idx[m * K_ + lt];
        rel_s[u][lt] = (xs[b * N_ + sj] - centers[m]) / RADIUS_;
        u_s[u][lt] = us[b * N_ + sj];
    }
    __syncthreads();

    {
        float w10 = W1[lt], w11 = W1[H_ + lt], bb1 = b1[lt];
#pragma unroll
        for (int k = 0; k < K_; k++)
            h1T[u][lt * K_ + k] = fmaxf(fmaf(rel_s[u][k], w10, fmaf(u_s[u][k], w11, bb1)), 0.f);
    }
    __syncthreads();

    float hbv;
    {
        float acc[K_];
        float bb2 = b2[lt];
#pragma unroll
        for (int k = 0; k < K_; k++) acc[k] = bb2;
        for (int jj = 0; jj < H_; jj++) {
            float wv = W2s[jj * H_ + lt];
            const float4* hp = (const float4*)(h1T[u] + jj * K_);
#pragma unroll
            for (int kk = 0; kk < 4; kk++) {
                float4 h4 = hp[kk];
                acc[kk * 4 + 0] = fmaf(h4.x, wv, acc[kk * 4 + 0]);
                acc[kk * 4 + 1] = fmaf(h4.y, wv, acc[kk * 4 + 1]);
                acc[kk * 4 + 2] = fmaf(h4.z, wv, acc[kk * 4 + 2]);
                acc[kk * 4 + 3] = fmaf(h4.w, wv, acc[kk * 4 + 3]);
            }
        }
        float accm = 0.f;
#pragma unroll
        for (int k = 0; k < K_; k++) accm += fmaxf(acc[k], 0.f);
        hbv = accm * (1.0f / (float)K_);
    }
    hb[u][lt] = hbv;
    __syncthreads();

    cudaGridDependencySynchronize();   // g_kernel results needed only below

    if (lt < D_) {
        float v = b3[lt];
#pragma unroll 8
        for (int h = 0; h < H_; h++) v = fmaf(hb[u][h], W3[h * D_ + lt], v);
        out[C0_OFF + bm * D_ + lt] = v + g_gw[b][lt];
    }
}

// ---------------- kernel 3: sheaf CG (register-R fold, templated NODES) ----------------
#define NT_CG 544   // 17 warps

__device__ __forceinline__ void edge_r_fn(const float (&Rs)[16], const float (&Rd)[16],
    const float* __restrict__ r_s, int rowA, float* __restrict__ re, int lane, int riMap)
{
    float a = r_s[rowA * 32 + lane];
    float c = r_s[rowA * 32 + 32 + lane];
    float v[16];
#pragma unroll
    for (int ri = 0; ri < 16; ri++) { v[ri] = Rs[ri] * a; v[ri] = fmaf(-Rd[ri], c, v[ri]); }
    {
        const bool bb = (lane & 16) != 0;
#pragma unroll
        for (int t = 0; t < 8; t++) {
            float snd = bb ? v[t] : v[t + 8];
            float kp  = bb ? v[t + 8] : v[t];
            v[t] = kp + __shfl_xor_sync(0xffffffffu, snd, 16);
        }
    }
    {
        const bool bb = (lane & 8) != 0;
#pragma unroll
        for (int t = 0; t < 4; t++) {
            float snd = bb ? v[t] : v[t + 4];
            float kp  = bb ? v[t + 4] : v[t];
            v[t] = kp + __shfl_xor_sync(0xffffffffu, snd, 8);
        }
    }
    {
        const bool bb = (lane & 4) != 0;
#pragma unroll
        for (int t = 0; t < 2; t++) {
            float snd = bb ? v[t] : v[t + 2];
            float kp  = bb ? v[t + 2] : v[t];
            v[t] = kp + __shfl_xor_sync(0xffffffffu, snd, 4);
        }
    }
    {
        const bool bb = (lane & 2) != 0;
        float snd = bb ? v[0] : v[1];
        float kp  = bb ? v[1] : v[0];
        v[0] = kp + __shfl_xor_sync(0xffffffffu, snd, 2);
    }
    v[0] += __shfl_xor_sync(0xffffffffu, v[0], 1);
    if ((lane & 1) == 0) re[riMap] = v[0];
}

__device__ __forceinline__ void edge_g_fn(const float (&Rs)[16], const float (&Rd)[16],
    const float* __restrict__ re, float* __restrict__ gs_o, float* __restrict__ gd_o, int lane)
{
    float gs = 0.f, gd = 0.f;
#pragma unroll
    for (int ri = 0; ri < 16; ri++) {
        float rv = re[ri];
        gs = fmaf(Rs[ri], rv, gs);
        gd = fmaf(Rd[ri], rv, gd);
    }
    gs_o[lane] = gs;
    gd_o[lane] = gd;
}

template<int NODES>
__global__ void __launch_bounds__(NT_CG, 1) cg_kernel_t(
    const float* __restrict__ Rsrc, const float* __restrict__ Rdst,
    float* __restrict__ out)
{
    constexpr int CPB  = M_ / NODES;
    constexpr int EPW  = NODES / 16;
    constexpr int MAXE = NODES + 1;
    constexpr int NEL  = NODES * 32;

    __shared__ float r_s[(NODES + 2) * 32];
    __shared__ float w_s[NEL];
    __shared__ float p_s[NEL];
    __shared__ float s_s[NEL];
    __shared__ float x_s[NEL];
    __shared__ float sh_[2][32];
    __shared__ float redge[MAXE * 16];
    __shared__ float gse[MAXE * 32], gde[MAXE * 32];
    __shared__ float part_in[2][CPB][2];
    __shared__ float rin[2][32];
    __shared__ float wb[2][2][32];
    __shared__ float wred[17][2];

    const int b = blockIdx.x / CPB, j = blockIdx.x % CPB;
    const int tid = threadIdx.x, w = tid >> 5, lane = tid & 31;
    const int n0 = j * NODES;
    const int eA = j ? (n0 - 1) : 0;
    const int eB = (n0 + NODES - 1) < 254 ? (n0 + NODES - 1) : 254;
    const int nE = eB - eA + 1;
    const int riMap = ((lane >> 4) & 1) * 8 + ((lane >> 3) & 1) * 4 +
                      ((lane >> 2) & 1) * 2 + ((lane >> 1) & 1);

    const int el0 = EPW * w, el1 = el0 + 1;
    const bool h0 = el0 < nE;
    const bool h1 = (EPW == 2) && (el1 < nE);
    const int row0 = eA + el0 - n0 + 1;
    const int row1 = row0 + 1;

    // independent prologue: R loads (overlaps encode's tail under PDL)
    float Rs0[16], Rd0[16], Rs1[16], Rd1[16];
    if (h0) {
        const float* a = Rsrc + (size_t)(eA + el0) * 512 + lane;
        const float* d = Rdst + (size_t)(eA + el0) * 512 + lane;
#pragma unroll
        for (int ri = 0; ri < 16; ri++) { Rs0[ri] = a[ri * 32]; Rd0[ri] = d[ri * 32]; }
    }
    if constexpr (EPW == 2) {
        if (h1) {
            const float* a = Rsrc + (size_t)(eA + el1) * 512 + lane;
            const float* d = Rdst + (size_t)(eA + el1) * 512 + lane;
#pragma unroll
            for (int ri = 0; ri < 16; ri++) { Rs1[ri] = a[ri * 32]; Rd1[ri] = d[ri * 32]; }
        }
    }

    auto apply_fused = [&](float& lg, float& ld) {
        if (h0) edge_r_fn(Rs0, Rd0, r_s, row0, &redge[el0 * 16], lane, riMap);
        if constexpr (EPW == 2) { if (h1) edge_r_fn(Rs1, Rd1, r_s, row1, &redge[el1 * 16], lane, riMap); }
        __syncwarp();
        if (h0) edge_g_fn(Rs0, Rd0, &redge[el0 * 16], &gse[el0 * 32], &gde[el0 * 32], lane);
        if constexpr (EPW == 2) { if (h1) edge_g_fn(Rs1, Rd1, &redge[el1 * 16], &gse[el1 * 32], &gde[el1 * 32], lane); }
        __syncthreads();
        for (int i = tid; i < NEL; i += NT_CG) {
            int n = n0 + (i >> 5), d = i & 31;
            float acc = 0.f;
            if (n <= 254) acc = gse[(n - eA) * 32 + d];
            if (n >= 1)  acc -= gde[(n - 1 - eA) * 32 + d];
            float rr = r_s[i + 32];
            float ww = fmaf(LAM_, acc, rr);
            w_s[i] = ww;
            lg = fmaf(rr, rr, lg);
            ld = fmaf(rr, ww, ld);
        }
    };
    auto reduce_export = [&](float lg, float ld, int buf) {
#pragma unroll
        for (int o = 16; o; o >>= 1) {
            lg += __shfl_xor_sync(0xffffffffu, lg, o);
            ld += __shfl_xor_sync(0xffffffffu, ld, o);
        }
        if (lane == 0) { wred[w][0] = lg; wred[w][1] = ld; }
        __syncthreads();
        if (tid < CPB) {
            float sg = 0.f, sd = 0.f;
#pragma unroll
            for (int k2 = 0; k2 < 17; k2++) { sg += wred[k2][0]; sd += wred[k2][1]; }
            st_cluster(mapa_rank(smem_u32(&part_in[buf][j][0]), (uint32_t)tid), sg);
            st_cluster(mapa_rank(smem_u32(&part_in[buf][j][1]), (uint32_t)tid), sd);
        }
    };
    auto whalo_send = [&](int buf) {
        if (tid >= 64 && tid < 96) {
            if (j > 0) st_cluster(mapa_rank(smem_u32(&wb[buf][1][tid - 64]), j - 1), w_s[tid - 64]);
        } else if (tid >= 96 && tid < 128) {
            if (j < CPB - 1) st_cluster(mapa_rank(smem_u32(&wb[buf][0][tid - 96]), j + 1),
                                        w_s[(NODES - 1) * 32 + tid - 96]);
        }
    };

    cudaGridDependencySynchronize();   // c0 (encode output) needed from here on

    const float* c0g = out + C0_OFF + b * (M_ * D_);
    for (int i = tid; i < (NODES + 2) * 32; i += NT_CG) {
        int node = n0 - 1 + (i >> 5);
        r_s[i] = (node >= 0 && node < M_) ? c0g[node * 32 + (i & 31)] : 0.f;
    }
    __syncthreads();
    for (int i = tid; i < NEL; i += NT_CG) x_s[i] = r_s[i + 32];
    __syncthreads();

    { float z0 = 0, z1 = 0; apply_fused(z0, z1); }
    __syncthreads();
    for (int i = tid; i < NEL; i += NT_CG) r_s[i + 32] = x_s[i] - w_s[i];
    __syncthreads();

    if (tid < 32) {
        if (j > 0) st_cluster(mapa_rank(smem_u32(&rin[1][tid]), j - 1), r_s[32 + tid]);
    } else if (tid < 64) {
        if (j < CPB - 1) st_cluster(mapa_rank(smem_u32(&rin[0][tid - 32]), j + 1), r_s[NODES * 32 + tid - 32]);
    }
    cluster_arrive_(); cluster_wait_();
    if (tid < 32) {
        if (j > 0) r_s[tid] = rin[0][tid];
    } else if (tid < 64) {
        if (j < CPB - 1) r_s[(NODES + 1) * 32 + (tid - 32)] = rin[1][tid - 32];
    }
    __syncthreads();

    float lg = 0.f, ld = 0.f;
    apply_fused(lg, ld);
    reduce_export(lg, ld, 0);
    whalo_send(0);
    cluster_arrive_(); cluster_wait_();

    float gam = 0.f, del = 0.f;
#pragma unroll
    for (int k2 = 0; k2 < CPB; k2++) { gam += part_in[0][k2][0]; del += part_in[0][k2][1]; }
    float alpha = gam / (del + 1e-12f);
    float gam_prev = gam, alpha_prev = alpha;
    float alphap = alpha;

    if (tid < 32) {
        if (j > 0) {
            float sv = wb[0][0][tid];
            sh_[0][tid] = sv;
            r_s[tid] = fmaf(-alpha, sv, r_s[tid]);
        }
    } else if (tid < 64) {
        if (j < CPB - 1) {
            int d2 = tid - 32;
            float sv = wb[0][1][d2];
            sh_[1][d2] = sv;
            r_s[(NODES + 1) * 32 + d2] = fmaf(-alpha, sv, r_s[(NODES + 1) * 32 + d2]);
        }
    }
    for (int i = tid; i < NEL; i += NT_CG) {
        float rr = r_s[i + 32], ww = w_s[i];
        p_s[i] = rr; s_s[i] = ww;
        r_s[i + 32] = fmaf(-alpha, ww, rr);
    }
    __syncthreads();

    for (int it = 1; it < CG_ITERS_; it++) {
        float g0 = 0.f, d0 = 0.f;
        apply_fused(g0, d0);
        const int buf = it & 1;
        reduce_export(g0, d0, buf);
        if (it < CG_ITERS_ - 1) whalo_send(buf);
        cluster_arrive_();
        for (int i = tid; i < NEL; i += NT_CG)
            x_s[i] = fmaf(alphap, p_s[i], x_s[i]);
        cluster_wait_();

        gam = 0.f; del = 0.f;
#pragma unroll
        for (int k2 = 0; k2 < CPB; k2++) { gam += part_in[buf][k2][0]; del += part_in[buf][k2][1]; }
        float beta = gam / (gam_prev + 1e-12f);
        alpha = gam / (del - beta * gam / alpha_prev + 1e-12f);
        gam_prev = gam; alpha_prev = alpha;

        if (it == CG_ITERS_ - 1) {
            float* og = out + C_OFF + b * (M_ * D_) + n0 * 32;
            for (int i = tid; i < NEL; i += NT_CG)
                og[i] = fmaf(alpha, fmaf(beta, p_s[i], r_s[i + 32]), x_s[i]);
            return;
        }
        alphap = alpha;

        if (tid < 32) {
            if (j > 0) {
                float sv = fmaf(beta, sh_[0][tid], wb[buf][0][tid]);
                sh_[0][tid] = sv;
                r_s[tid] = fmaf(-alpha, sv, r_s[tid]);
            }
        } else if (tid < 64) {
            if (j < CPB - 1) {
                int d2 = tid - 32;
                float sv = fmaf(beta, sh_[1][d2], wb[buf][1][d2]);
                sh_[1][d2] = sv;
                r_s[(NODES + 1) * 32 + d2] = fmaf(-alpha, sv, r_s[(NODES + 1) * 32 + d2]);
            }
        }
        for (int i = tid; i < NEL; i += NT_CG) {
            float rr = r_s[i + 32], ww = w_s[i];
            float pp = fmaf(beta, p_s[i], rr);
            float ss = fmaf(beta, s_s[i], ww);
            r_s[i + 32] = fmaf(-alpha, ss, rr);
            p_s[i] = pp; s_s[i] = ss;
        }
        __syncthreads();
    }
}

// ---------------- kernel 4: query (PDL: phi prefetch BEFORE griddep sync) ----------------
__global__ void __launch_bounds__(256) query_kernel(
    const float* __restrict__ phi_q, const float* __restrict__ out_c,
    float* __restrict__ out)
{
    __shared__ float4 c_s[512];
    int q0 = blockIdx.x * 64;
    int mbase = (int)floorf((q0 + 0.5f) * 0.015625f) - 2;
    if (mbase < 0) mbase = 0;
    if (mbase > M_ - 8) mbase = M_ - 8;

    int ql = threadIdx.x >> 2;
    int dh = (threadIdx.x >> 1) & 1;
    int bh = threadIdx.x & 1;
    int q = q0 + ql;
    float v = (q + 0.5f) * 0.015625f;
    int mlo = (int)floorf(v) - 1;

    // independent prefetch of all 3 candidate phi rows (overlaps cg tail under PDL)
    float wr[3];
    float4 p4[3][4];
    int mc[3];
#pragma unroll
    for (int c = 0; c < 3; c++) {
        int m = mlo + c;
        int mcl = m < 0 ? 0 : (m > M_ - 1 ? M_ - 1 : m);
        mc[c] = mcl;
        const float4* ph = (const float4*)(phi_q + ((size_t)mcl * Q_ + q) * 32) + dh * 4;
        p4[c][0] = __ldg(ph + 0);
        p4[c][1] = __ldg(ph + 1);
        p4[c][2] = __ldg(ph + 2);
        p4[c][3] = __ldg(ph + 3);
        float t = (v - (m + 0.5f)) * (1.0f / 1.5f);
        float w_ = 1.0f - fabsf(t);
        wr[c] = (m >= 0 && m <= M_ - 1) ? fmaxf(w_, 0.f) : 0.f;
    }
    float wsum = wr[0] + wr[1] + wr[2];

    cudaGridDependencySynchronize();   // c (cg output) needed from here on

    const float4* cg4 = (const float4*)out_c;
    for (int i = threadIdx.x; i < 512; i += 256) {
        int mm = i >> 6, rem = i & 63;
        int bb2 = rem >> 3, d4 = rem & 7;
        c_s[i] = cg4[((size_t)bb2 * M_ + (mbase + mm)) * 8 + d4];
    }
    __syncthreads();

    float sacc[4] = {0.f, 0.f, 0.f, 0.f};
#pragma unroll
    for (int c = 0; c < 3; c++) {
        int ms = mc[c] - mbase;
#pragma unroll
        for (int bb2 = 0; bb2 < 4; bb2++) {
            const float4* cc = &c_s[(ms << 6) + ((bh * 4 + bb2) << 3) + dh * 4];
            float dot = 0.f;
#pragma unroll
            for (int i = 0; i < 4; i++) {
                float4 c4 = cc[i];
                float4 pp = p4[c][i];
                dot = fmaf(pp.x, c4.x, dot);
                dot = fmaf(pp.y, c4.y, dot);
                dot = fmaf(pp.z, c4.z, dot);
                dot = fmaf(pp.w, c4.w, dot);
            }
            sacc[bb2] = fmaf(wr[c], dot, sacc[bb2]);
        }
    }
#pragma unroll
    for (int bb2 = 0; bb2 < 4; bb2++)
        sacc[bb2] += __shfl_xor_sync(0xffffffffu, sacc[bb2], 2);
    if (dh == 0) {
        float inv = 1.0f / fmaxf(wsum, 1e-8f);
#pragma unroll
        for (int bb2 = 0; bb2 < 4; bb2++)
            out[(size_t)(bh * 4 + bb2) * Q_ + q] = sacc[bb2] * inv;
    }
}

// ---------------- launch ----------------
extern "C" void kernel_launch(void* const* d_in, const int* in_sizes, int n_in,
                              void* d_out, int out_size) {
    const float* xs      = (const float*)d_in[0];
    const float* us      = (const float*)d_in[1];
    const float* phi_q   = (const float*)d_in[2];
    const float* centers = (const float*)d_in[4];
    const float* R_src   = (const float*)d_in[5];
    const float* R_dst   = (const float*)d_in[6];
    const float* W1      = (const float*)d_in[7];
    const float* b1      = (const float*)d_in[8];
    const float* W2      = (const float*)d_in[9];
    const float* b2      = (const float*)d_in[10];
    const float* W3      = (const float*)d_in[11];
    const float* b3      = (const float*)d_in[12];
    const float* Wg1     = (const float*)d_in[13];
    const float* bg1     = (const float*)d_in[14];
    const float* Wg2     = (const float*)d_in[15];
    const float* bg2     = (const float*)d_in[16];
    const int*   idx     = (const int*)d_in[17];
    float* out = (float*)d_out;

    g_kernel<<<B_, 1024>>>(xs, us, Wg1, bg1, Wg2, bg2);

    // encode: PDL-chained after g
    {
        cudaLaunchAttribute a[1];
        a[0].id = cudaLaunchAttributeProgrammaticStreamSerialization;
        a[0].val.programmaticStreamSerializationAllowed = 1;
        cudaLaunchConfig_t c = {};
        c.gridDim = dim3(B_ * M_ / 4, 1, 1);
        c.blockDim = dim3(256, 1, 1);
        c.attrs = a; c.numAttrs = 1; c.stream = 0;
        if (cudaLaunchKernelEx(&c, encode_kernel, xs, us, centers, W1, b1, W2, b2,
                               W3, b3, idx, out) != cudaSuccess)
            encode_kernel<<<B_ * M_ / 4, 256>>>(xs, us, centers, W1, b1, W2, b2, W3, b3, idx, out);
    }

    // cg: cluster-8 + PDL-chained after encode
    {
        cudaLaunchAttribute a[2];
        a[0].id = cudaLaunchAttributeClusterDimension;
        a[0].val.clusterDim = {8, 1, 1};
        a[1].id = cudaLaunchAttributeProgrammaticStreamSerialization;
        a[1].val.programmaticStreamSerializationAllowed = 1;
        cudaLaunchConfig_t c = {};
        c.gridDim = dim3(B_ * 8, 1, 1);
        c.blockDim = dim3(NT_CG, 1, 1);
        c.attrs = a; c.numAttrs = 2; c.stream = 0;
        if (cudaLaunchKernelEx(&c, cg_kernel_t<32>, R_src, R_dst, out) != cudaSuccess) {
            cudaLaunchConfig_t c1 = c;
            c1.numAttrs = 1;   // cluster only
            cudaLaunchKernelEx(&c1, cg_kernel_t<32>, R_src, R_dst, out);
        }
    }

    // query: PDL-chained after cg
    {
        cudaLaunchAttribute a[1];
        a[0].id = cudaLaunchAttributeProgrammaticStreamSerialization;
        a[0].val.programmaticStreamSerializationAllowed = 1;
        cudaLaunchConfig_t c = {};
        c.gridDim = dim3(Q_ / 64, 1, 1);
        c.blockDim = dim3(256, 1, 1);
        c.attrs = a; c.numAttrs = 1; c.stream = 0;
        if (cudaLaunchKernelEx(&c, query_kernel, phi_q, out + C_OFF, out) != cudaSuccess)
            query_kernel<<<Q_ / 64, 256>>>(phi_q, out + C_OFF, out);
    }
}